// round 3
// baseline (speedup 1.0000x reference)
#include <cuda_runtime.h>
#include <cuda_fp16.h>
#include <cstdint>

#define H    32
#define KP   15
#define QPB  16
#define NKS  60                 // 960 / 16 k-steps
#define KPE_INV (1.0f/1.2f)

// ---- smem layout (bytes) ----
#define OFF_FRAG 0              // A-frags: 60*32*4 u32 = 30720
#define OFF_LIST 30720          // lists:  16*15*32 u32 = 30720
#define OFF_CNT  61440          // counts: 16*16 u32    = 1024
#define OFF_INVC 62464          // 16 floats
#define OFF_KP   62528          // 48 floats
#define SMEM_BYTES 62720

__device__ float4   g_spts4[50000];          // (x,y,z,validity)
__device__ unsigned g_Wfrag[8 * NKS * 32 * 2];  // fp16 B-fragments, fragment order

// ---------- prep 1: pack support points + validity flag ----------
__global__ void pack_kernel(const float* __restrict__ x,
                            const float* __restrict__ s_pts, int M) {
    int row  = (blockIdx.x * blockDim.x + threadIdx.x) >> 5;
    int lane = threadIdx.x & 31;
    if (row >= M) return;
    float s = x[row * 64 + lane] + x[row * 64 + 32 + lane];
    #pragma unroll
    for (int o = 16; o; o >>= 1) s += __shfl_xor_sync(0xffffffffu, s, o);
    if (lane == 0)
        g_spts4[row] = make_float4(s_pts[row*3], s_pts[row*3+1], s_pts[row*3+2],
                                   (s > 0.0f) ? 1.0f : 0.0f);
}

// ---------- prep 2: W -> fp16 B-fragment order ----------
// m16n8k16 B frag: reg r holds halves (k = 2*tid + 8r, +1), col = gid.
__global__ void wfrag_kernel(const float* __restrict__ W) {
    int t = blockIdx.x * blockDim.x + threadIdx.x;
    if (t >= 8 * NKS * 32 * 2) return;
    int reg  = t & 1;
    int lane = (t >> 1) & 31;
    int rest = t >> 6;
    int ks   = rest % NKS;
    int nblk = rest / NKS;
    int col  = nblk * 8 + (lane >> 2);
    int kk0  = ks * 16 + 2 * (lane & 3) + 8 * reg;
    __half2 h = __floats2half2_rn(W[kk0 * 64 + col], W[(kk0 + 1) * 64 + col]);
    g_Wfrag[t] = *reinterpret_cast<unsigned*>(&h);
}

// ---------- main fused kernel ----------
__global__ void __launch_bounds__(512, 2)
kpconv_kernel(const float* __restrict__ q_pts,
              const int*   __restrict__ inds,
              const float* __restrict__ x,
              const float* __restrict__ kpts,
              float*       __restrict__ out)
{
    extern __shared__ char smem[];
    unsigned* frag   = (unsigned*)(smem + OFF_FRAG);
    unsigned* list   = (unsigned*)(smem + OFF_LIST);
    unsigned* cnt_sm = (unsigned*)(smem + OFF_CNT);
    float*    invc   = (float*)(smem + OFF_INVC);
    float*    kp_sm  = (float*)(smem + OFF_KP);

    const int tid  = threadIdx.x;
    const int warp = tid >> 5;
    const int lane = tid & 31;

    if (tid < KP * 3) kp_sm[tid] = kpts[tid];
    __syncthreads();

    const int n = blockIdx.x * QPB + warp;

    // ---- Phase A: lane = neighbor h; build sparse (ind,w) lists per kernel point ----
    {
        int ind = inds[n * H + lane];
        float4 sp = __ldg(&g_spts4[ind]);
        float qx = __ldg(&q_pts[n*3+0]);
        float qy = __ldg(&q_pts[n*3+1]);
        float qz = __ldg(&q_pts[n*3+2]);
        float dx = sp.x - qx, dy = sp.y - qy, dz = sp.z - qz;

        unsigned mv = __ballot_sync(0xffffffffu, sp.w > 0.5f);
        if (lane == 0) {
            int c = __popc(mv); if (c < 1) c = 1;
            invc[warp] = 1.0f / (float)c;
        }

        unsigned encb  = ((unsigned)ind) << 16;
        unsigned lmask = (1u << lane) - 1u;
        #pragma unroll
        for (int k = 0; k < KP; k++) {
            float ex = dx - kp_sm[k*3+0];
            float ey = dy - kp_sm[k*3+1];
            float ez = dz - kp_sm[k*3+2];
            float d2 = fmaf(ex, ex, fmaf(ey, ey, ez * ez));
            float w  = 1.0f - sqrtf(d2) * KPE_INV;
            unsigned m = __ballot_sync(0xffffffffu, w > 0.0f);
            if (w > 0.0f) {
                unsigned w16 = (unsigned)(w * 65536.0f + 0.5f);
                if (w16 > 65535u) w16 = 65535u;
                int pos = __popc(m & lmask);
                list[(warp * KP + k) * 32 + pos] = encb | w16;
            }
            if (lane == 0) cnt_sm[warp * 16 + k] = __popc(m);
        }
    }
    __syncwarp();

    // ---- Phase B: lane = channel pair (2*lane, 2*lane+1); sparse accumulation ----
    const float2* __restrict__ x2 = (const float2*)x;
    float ax[KP], ay[KP];
    #pragma unroll
    for (int k = 0; k < KP; k++) { ax[k] = 0.0f; ay[k] = 0.0f; }

    #pragma unroll
    for (int k = 0; k < KP; k++) {
        const int cnt = (int)cnt_sm[warp * 16 + k];
        const uint4* lp = (const uint4*)&list[(warp * KP + k) * 32];
        for (int s0 = 0; s0 < cnt; s0 += 4) {
            uint4 e4 = lp[s0 >> 2];
            float w0 = 0.f, w1 = 0.f, w2 = 0.f, w3 = 0.f;
            float2 v0 = {0.f,0.f}, v1 = {0.f,0.f}, v2 = {0.f,0.f}, v3 = {0.f,0.f};
            if (s0 + 0 < cnt) { w0 = (float)(e4.x & 0xFFFFu); v0 = __ldg(&x2[(e4.x >> 16) * 32 + lane]); }
            if (s0 + 1 < cnt) { w1 = (float)(e4.y & 0xFFFFu); v1 = __ldg(&x2[(e4.y >> 16) * 32 + lane]); }
            if (s0 + 2 < cnt) { w2 = (float)(e4.z & 0xFFFFu); v2 = __ldg(&x2[(e4.z >> 16) * 32 + lane]); }
            if (s0 + 3 < cnt) { w3 = (float)(e4.w & 0xFFFFu); v3 = __ldg(&x2[(e4.w >> 16) * 32 + lane]); }
            ax[k] = fmaf(w0, v0.x, ax[k]);  ay[k] = fmaf(w0, v0.y, ay[k]);
            ax[k] = fmaf(w1, v1.x, ax[k]);  ay[k] = fmaf(w1, v1.y, ay[k]);
            ax[k] = fmaf(w2, v2.x, ax[k]);  ay[k] = fmaf(w2, v2.y, ay[k]);
            ax[k] = fmaf(w3, v3.x, ax[k]);  ay[k] = fmaf(w3, v3.y, ay[k]);
        }
    }

    // ---- store A-fragments (fp16, MMA layout) ----
    // value (row q, kk=k*64+2*lane): ks = k*4 + (lane>>3); frag lane' = (q&7)*4 + (lane&3);
    // reg = (q>>3) + 2*((lane>>2)&1); half2 = (even, odd channel).
    {
        const float sc = 1.0f / 65536.0f;        // undo w fixed-point scale
        const int   fl = (warp & 7) * 4 + (lane & 3);
        const int   rg = (warp >> 3) + 2 * ((lane >> 2) & 1);
        const int   kb = lane >> 3;
        #pragma unroll
        for (int k = 0; k < KP; k++) {
            __half2 h = __floats2half2_rn(ax[k] * sc, ay[k] * sc);
            frag[(k * 4 + kb) * 128 + fl * 4 + rg] = *reinterpret_cast<unsigned*>(&h);
        }
    }
    __syncthreads();

    // ---- Phase C: warps 0..7 — fp16 MMA [16 x 960] @ [960 x 64] ----
    if (warp < 8) {
        const int nblk = warp;
        const uint2* __restrict__ wf = (const uint2*)g_Wfrag + (nblk * NKS) * 32 + lane;
        float c0 = 0.f, c1 = 0.f, c2 = 0.f, c3 = 0.f;

        #pragma unroll 4
        for (int ks = 0; ks < NKS; ks++) {
            uint4 a = *(const uint4*)&frag[ks * 128 + lane * 4];
            uint2 b = __ldg(&wf[ks * 32]);
            asm volatile(
                "mma.sync.aligned.m16n8k16.row.col.f32.f16.f16.f32 "
                "{%0,%1,%2,%3}, {%4,%5,%6,%7}, {%8,%9}, {%0,%1,%2,%3};"
                : "+f"(c0), "+f"(c1), "+f"(c2), "+f"(c3)
                : "r"(a.x), "r"(a.y), "r"(a.z), "r"(a.w), "r"(b.x), "r"(b.y));
        }

        const int grp = lane >> 2, tq = lane & 3;
        float s0 = invc[grp], s1 = invc[grp + 8];
        int n0  = blockIdx.x * QPB + grp;
        int col = nblk * 8 + tq * 2;
        *(float2*)&out[n0 * 64 + col]       = make_float2(c0 * s0, c1 * s0);
        *(float2*)&out[(n0 + 8) * 64 + col] = make_float2(c2 * s1, c3 * s1);
    }
}

extern "C" void kernel_launch(void* const* d_in, const int* in_sizes, int n_in,
                              void* d_out, int out_size) {
    const float* q_pts = (const float*)d_in[0];
    const float* s_pts = (const float*)d_in[1];
    const int*   inds  = (const int*)d_in[2];
    const float* x     = (const float*)d_in[3];
    const float* kpts  = (const float*)d_in[4];
    const float* W     = (const float*)d_in[5];
    float*       out   = (float*)d_out;

    const int N = in_sizes[0] / 3;
    const int M = in_sizes[1] / 3;

    cudaFuncSetAttribute(kpconv_kernel,
                         cudaFuncAttributeMaxDynamicSharedMemorySize, SMEM_BYTES);

    pack_kernel<<<(M + 7) / 8, 256>>>(x, s_pts, M);
    wfrag_kernel<<<(8 * NKS * 32 * 2 + 255) / 256, 256>>>(W);
    kpconv_kernel<<<N / QPB, 512, SMEM_BYTES>>>(q_pts, inds, x, kpts, out);
}

// round 4
// speedup vs baseline: 1.0036x; 1.0036x over previous
#include <cuda_runtime.h>
#include <cuda_fp16.h>
#include <cstdint>

#define H    32
#define KP   15
#define QPB  16
#define NKS  60                 // 960 / 16 k-steps
#define KPE_INV (1.0f/1.2f)

// ---- smem layout (bytes) ----
#define OFF_FRAG 0              // A-frags: 60*32*4 u32 = 30720
#define OFF_LIST 30720          // lists:  16*15*32 u32 = 30720
#define OFF_CNT  61440          // counts: 16*16 u32    = 1024
#define OFF_INVC 62464          // 16 floats
#define OFF_KP   62528          // 48 floats
#define SMEM_BYTES 62720

__device__ float4   g_spts4[50000];          // (x,y,z,validity)
__device__ unsigned g_Wfrag[8 * NKS * 32 * 2];  // fp16 B-fragments, fragment order

// ---------- prep 1: pack support points + validity flag ----------
__global__ void pack_kernel(const float* __restrict__ x,
                            const float* __restrict__ s_pts, int M) {
    int row  = (blockIdx.x * blockDim.x + threadIdx.x) >> 5;
    int lane = threadIdx.x & 31;
    if (row >= M) return;
    float s = x[row * 64 + lane] + x[row * 64 + 32 + lane];
    #pragma unroll
    for (int o = 16; o; o >>= 1) s += __shfl_xor_sync(0xffffffffu, s, o);
    if (lane == 0)
        g_spts4[row] = make_float4(s_pts[row*3], s_pts[row*3+1], s_pts[row*3+2],
                                   (s > 0.0f) ? 1.0f : 0.0f);
}

// ---------- prep 2: W -> fp16 B-fragment order ----------
// m16n8k16 B frag: reg r holds halves (k = 2*tid + 8r, +1), col = gid.
__global__ void wfrag_kernel(const float* __restrict__ W) {
    int t = blockIdx.x * blockDim.x + threadIdx.x;
    if (t >= 8 * NKS * 32 * 2) return;
    int reg  = t & 1;
    int lane = (t >> 1) & 31;
    int rest = t >> 6;
    int ks   = rest % NKS;
    int nblk = rest / NKS;
    int col  = nblk * 8 + (lane >> 2);
    int kk0  = ks * 16 + 2 * (lane & 3) + 8 * reg;
    __half2 h = __floats2half2_rn(W[kk0 * 64 + col], W[(kk0 + 1) * 64 + col]);
    g_Wfrag[t] = *reinterpret_cast<unsigned*>(&h);
}

// ---------- main fused kernel ----------
__global__ void __launch_bounds__(512, 2)
kpconv_kernel(const float* __restrict__ q_pts,
              const int*   __restrict__ inds,
              const float* __restrict__ x,
              const float* __restrict__ kpts,
              float*       __restrict__ out)
{
    extern __shared__ char smem[];
    unsigned* frag   = (unsigned*)(smem + OFF_FRAG);
    unsigned* list   = (unsigned*)(smem + OFF_LIST);
    unsigned* cnt_sm = (unsigned*)(smem + OFF_CNT);
    float*    invc   = (float*)(smem + OFF_INVC);
    float*    kp_sm  = (float*)(smem + OFF_KP);

    const int tid  = threadIdx.x;
    const int warp = tid >> 5;
    const int lane = tid & 31;

    if (tid < KP * 3) kp_sm[tid] = kpts[tid];
    __syncthreads();

    const int n = blockIdx.x * QPB + warp;

    // ---- Phase A: lane = neighbor h; build sparse (ind,w) lists per kernel point ----
    {
        int ind = inds[n * H + lane];
        float4 sp = __ldg(&g_spts4[ind]);
        float qx = __ldg(&q_pts[n*3+0]);
        float qy = __ldg(&q_pts[n*3+1]);
        float qz = __ldg(&q_pts[n*3+2]);
        float dx = sp.x - qx, dy = sp.y - qy, dz = sp.z - qz;

        unsigned mv = __ballot_sync(0xffffffffu, sp.w > 0.5f);
        if (lane == 0) {
            int c = __popc(mv); if (c < 1) c = 1;
            invc[warp] = 1.0f / (float)c;
        }

        unsigned encb  = ((unsigned)ind) << 16;
        unsigned lmask = (1u << lane) - 1u;
        #pragma unroll
        for (int k = 0; k < KP; k++) {
            float ex = dx - kp_sm[k*3+0];
            float ey = dy - kp_sm[k*3+1];
            float ez = dz - kp_sm[k*3+2];
            float d2 = fmaf(ex, ex, fmaf(ey, ey, ez * ez));
            float w  = 1.0f - sqrtf(d2) * KPE_INV;
            unsigned m = __ballot_sync(0xffffffffu, w > 0.0f);
            if (w > 0.0f) {
                unsigned w16 = (unsigned)(w * 65536.0f + 0.5f);
                if (w16 > 65535u) w16 = 65535u;
                int pos = __popc(m & lmask);
                list[(warp * KP + k) * 32 + pos] = encb | w16;
            }
            if (lane == 0) cnt_sm[warp * 16 + k] = __popc(m);
        }
    }
    __syncwarp();

    // ---- Phase B: lane = channel pair (2*lane, 2*lane+1); sparse accumulation ----
    const float2* __restrict__ x2 = (const float2*)x;
    float ax[KP], ay[KP];
    #pragma unroll
    for (int k = 0; k < KP; k++) { ax[k] = 0.0f; ay[k] = 0.0f; }

    #pragma unroll
    for (int k = 0; k < KP; k++) {
        const int cnt = (int)cnt_sm[warp * 16 + k];
        const uint4* lp = (const uint4*)&list[(warp * KP + k) * 32];
        for (int s0 = 0; s0 < cnt; s0 += 4) {
            uint4 e4 = lp[s0 >> 2];
            float w0 = 0.f, w1 = 0.f, w2 = 0.f, w3 = 0.f;
            float2 v0 = {0.f,0.f}, v1 = {0.f,0.f}, v2 = {0.f,0.f}, v3 = {0.f,0.f};
            if (s0 + 0 < cnt) { w0 = (float)(e4.x & 0xFFFFu); v0 = __ldg(&x2[(e4.x >> 16) * 32 + lane]); }
            if (s0 + 1 < cnt) { w1 = (float)(e4.y & 0xFFFFu); v1 = __ldg(&x2[(e4.y >> 16) * 32 + lane]); }
            if (s0 + 2 < cnt) { w2 = (float)(e4.z & 0xFFFFu); v2 = __ldg(&x2[(e4.z >> 16) * 32 + lane]); }
            if (s0 + 3 < cnt) { w3 = (float)(e4.w & 0xFFFFu); v3 = __ldg(&x2[(e4.w >> 16) * 32 + lane]); }
            ax[k] = fmaf(w0, v0.x, ax[k]);  ay[k] = fmaf(w0, v0.y, ay[k]);
            ax[k] = fmaf(w1, v1.x, ax[k]);  ay[k] = fmaf(w1, v1.y, ay[k]);
            ax[k] = fmaf(w2, v2.x, ax[k]);  ay[k] = fmaf(w2, v2.y, ay[k]);
            ax[k] = fmaf(w3, v3.x, ax[k]);  ay[k] = fmaf(w3, v3.y, ay[k]);
        }
    }

    // ---- store A-fragments (fp16, MMA layout) ----
    // value (row q, kk=k*64+2*lane): ks = k*4 + (lane>>3); frag lane' = (q&7)*4 + (lane&3);
    // reg = (q>>3) + 2*((lane>>2)&1); half2 = (even, odd channel).
    {
        const float sc = 1.0f / 65536.0f;        // undo w fixed-point scale
        const int   fl = (warp & 7) * 4 + (lane & 3);
        const int   rg = (warp >> 3) + 2 * ((lane >> 2) & 1);
        const int   kb = lane >> 3;
        #pragma unroll
        for (int k = 0; k < KP; k++) {
            __half2 h = __floats2half2_rn(ax[k] * sc, ay[k] * sc);
            frag[(k * 4 + kb) * 128 + fl * 4 + rg] = *reinterpret_cast<unsigned*>(&h);
        }
    }
    __syncthreads();

    // ---- Phase C: warps 0..7 — fp16 MMA [16 x 960] @ [960 x 64] ----
    if (warp < 8) {
        const int nblk = warp;
        const uint2* __restrict__ wf = (const uint2*)g_Wfrag + (nblk * NKS) * 32 + lane;
        float c0 = 0.f, c1 = 0.f, c2 = 0.f, c3 = 0.f;

        #pragma unroll 4
        for (int ks = 0; ks < NKS; ks++) {
            uint4 a = *(const uint4*)&frag[ks * 128 + lane * 4];
            uint2 b = __ldg(&wf[ks * 32]);
            asm volatile(
                "mma.sync.aligned.m16n8k16.row.col.f32.f16.f16.f32 "
                "{%0,%1,%2,%3}, {%4,%5,%6,%7}, {%8,%9}, {%0,%1,%2,%3};"
                : "+f"(c0), "+f"(c1), "+f"(c2), "+f"(c3)
                : "r"(a.x), "r"(a.y), "r"(a.z), "r"(a.w), "r"(b.x), "r"(b.y));
        }

        const int grp = lane >> 2, tq = lane & 3;
        float s0 = invc[grp], s1 = invc[grp + 8];
        int n0  = blockIdx.x * QPB + grp;
        int col = nblk * 8 + tq * 2;
        *(float2*)&out[n0 * 64 + col]       = make_float2(c0 * s0, c1 * s0);
        *(float2*)&out[(n0 + 8) * 64 + col] = make_float2(c2 * s1, c3 * s1);
    }
}

extern "C" void kernel_launch(void* const* d_in, const int* in_sizes, int n_in,
                              void* d_out, int out_size) {
    const float* q_pts = (const float*)d_in[0];
    const float* s_pts = (const float*)d_in[1];
    const int*   inds  = (const int*)d_in[2];
    const float* x     = (const float*)d_in[3];
    const float* kpts  = (const float*)d_in[4];
    const float* W     = (const float*)d_in[5];
    float*       out   = (float*)d_out;

    const int N = in_sizes[0] / 3;
    const int M = in_sizes[1] / 3;

    cudaFuncSetAttribute(kpconv_kernel,
                         cudaFuncAttributeMaxDynamicSharedMemorySize, SMEM_BYTES);

    pack_kernel<<<(M + 7) / 8, 256>>>(x, s_pts, M);
    wfrag_kernel<<<(8 * NKS * 32 * 2 + 255) / 256, 256>>>(W);
    kpconv_kernel<<<N / QPB, 512, SMEM_BYTES>>>(q_pts, inds, x, kpts, out);
}